// round 9
// baseline (speedup 1.0000x reference)
#include <cuda_runtime.h>
#include <cuda_fp16.h>
#include <math.h>
#include <stdint.h>

// Problem constants
#define TT   243
#define PP   17
#define LL   4
#define CC   128
#define HH   8
#define NPT  4
#define DHH  16
#define BB   2
#define LQ   (TT*PP*LL)        // 16524
#define BLQ  (BB*LQ)           // 33048
#define NLVL 5
#define BTP  (BB*TT*PP)        // 8262
#define TOK  (BTP*NLVL)        // 41310
#define SS   (PP*NLVL)         // 85

// ---------------- scratch (device globals; no allocations) ----------------
__device__ float  g_XS   [(size_t)BLQ*CC];
__device__ float  g_XCAT [(size_t)TOK*CC];
__device__ float  g_XCAT2[(size_t)TOK*CC];
__device__ __half g_OFFAWh[(size_t)BLQ*384];
__device__ __half g_Qh   [(size_t)BLQ*CC];
__device__ __half g_XNh  [(size_t)BLQ*CC];
__device__ __half g_VALh [(size_t)BLQ*CC];
__device__ __half g_Oh   [(size_t)BLQ*CC];
__device__ __half g_XN2h [(size_t)TOK*CC];
__device__ __half g_QKVh [(size_t)TOK*384];
__device__ __half g_ATTOh[(size_t)TOK*CC];
__device__ __half g_XN3h [(size_t)TOK*CC];
__device__ __half g_HIDh [(size_t)TOK*512];
#define WOFF_OFF   0
#define WOFF_ATTN  32768
#define WOFF_VAL   49152
#define WOFF_OUT   65536
#define WOFF_IN    81920
#define WOFF_OUTW  131072
#define WOFF_FC1   147456
#define WOFF_FC2   212992
#define WTOTAL     278528
__device__ __half g_Wh[WTOTAL];
__device__ float  g_Bcat[384];

// ---------------- PTX helpers ----------------------------------------------
__device__ __forceinline__ void cpa16(uint32_t dst, const void* src, bool valid) {
    int sz = valid ? 16 : 0;
    asm volatile("cp.async.cg.shared.global [%0], [%1], 16, %2;\n"
                 :: "r"(dst), "l"(src), "r"(sz));
}
#define CP_COMMIT() asm volatile("cp.async.commit_group;\n" ::: "memory")
#define CP_WAIT(n)  asm volatile("cp.async.wait_group %0;\n" :: "n"(n) : "memory")

__device__ __forceinline__ void ldm4(uint32_t* r, uint32_t addr) {
    asm volatile("ldmatrix.sync.aligned.m8n8.x4.shared.b16 {%0,%1,%2,%3}, [%4];\n"
                 : "=r"(r[0]), "=r"(r[1]), "=r"(r[2]), "=r"(r[3]) : "r"(addr));
}
__device__ __forceinline__ void mma16(float* c, const uint32_t* a, const uint32_t* b) {
    asm volatile("mma.sync.aligned.m16n8k16.row.col.f32.f16.f16.f32 "
                 "{%0,%1,%2,%3},{%4,%5,%6,%7},{%8,%9},{%0,%1,%2,%3};\n"
                 : "+f"(c[0]), "+f"(c[1]), "+f"(c[2]), "+f"(c[3])
                 : "r"(a[0]), "r"(a[1]), "r"(a[2]), "r"(a[3]), "r"(b[0]), "r"(b[1]));
}

// permuted destination row for the xcat concat
__device__ __forceinline__ int xcat_row(int gm) {
    int b = gm / LQ;
    int rem = gm - b * LQ;
    return (b * (TT * PP) + (rem >> 2)) * 5 + (rem & 3) + 1;
}

// ============================================================================
// BIG GEMM: BM=128, BN=128, BK=64, 256 threads, double-buffered (R3-proven).
// Used for wide-N / large GEMMs to halve weight traffic.
// epi: 0=bias, 1=bias+res, 2=bias+GELU
// smem: 2 stages x 32KB = 65536
// ============================================================================
#define BIG_STG  32768
#define BIG_SMEM 65536

__device__ __forceinline__ void big_load_stage(
    const __half* __restrict__ A, const __half* __restrict__ W, uint32_t sb,
    int st, int kt, int row0, int col0, int M, int K, int tid)
{
    const int r0 = tid >> 3, ck = tid & 7;
    const uint32_t base = sb + st * BIG_STG;
#pragma unroll
    for (int i = 0; i < 4; i++) {
        int r = r0 + i * 32;
        uint32_t swoff = (uint32_t)(r * 128 + ((ck ^ (r & 7)) * 16));
        int gm = row0 + r;
        cpa16(base + swoff, A + (size_t)gm * K + (size_t)kt * 64 + ck * 8, gm < M);
        cpa16(base + 16384 + swoff,
              W + (size_t)(col0 + r) * K + (size_t)kt * 64 + ck * 8, true);
    }
}

__global__ __launch_bounds__(256, 2) void k_gemm_big(
    const __half* __restrict__ A, const __half* __restrict__ W,
    const float* __restrict__ bias, const float* __restrict__ res,
    void* __restrict__ outp, int M, int N, int K, int epi, int outHalf)
{
    extern __shared__ __align__(1024) char sm[];
    uint32_t sb = (uint32_t)__cvta_generic_to_shared(sm);
    const int tid = threadIdx.x, lane = tid & 31, warp = tid >> 5;
    const int g = lane >> 2, t = lane & 3;
    const int wm = (warp >> 1) * 32, wn = (warp & 1) * 64;
    const int row0 = blockIdx.y * 128, col0 = blockIdx.x * 128;
    const int KT = K >> 6;

    float acc[2][8][4];
#pragma unroll
    for (int mi = 0; mi < 2; mi++)
#pragma unroll
        for (int ni = 0; ni < 8; ni++)
#pragma unroll
            for (int r = 0; r < 4; r++) acc[mi][ni][r] = 0.f;

    big_load_stage(A, W, sb, 0, 0, row0, col0, M, K, tid);
    CP_COMMIT();

    for (int kt = 0; kt < KT; kt++) {
        const int s = kt & 1;
        if (kt + 1 < KT) {
            big_load_stage(A, W, sb, s ^ 1, kt + 1, row0, col0, M, K, tid);
            CP_COMMIT();
            CP_WAIT(1);
        } else {
            CP_WAIT(0);
        }
        __syncthreads();

        const uint32_t aS = sb + s * BIG_STG;
        const uint32_t bS = aS + 16384;
        const int rlow = lane & 15, hi = lane >> 4;
#pragma unroll
        for (int kk = 0; kk < 4; kk++) {
            uint32_t af[2][4];
#pragma unroll
            for (int mi = 0; mi < 2; mi++) {
                int r = wm + mi * 16 + rlow;
                int ck = kk * 2 + hi;
                ldm4(af[mi], aS + (uint32_t)(r * 128 + ((ck ^ (r & 7)) * 16)));
            }
            uint32_t bf[8][2];
#pragma unroll
            for (int nj = 0; nj < 4; nj++) {
                int r = wn + nj * 16 + rlow;
                int ck = kk * 2 + hi;
                uint32_t q[4];
                ldm4(q, bS + (uint32_t)(r * 128 + ((ck ^ (r & 7)) * 16)));
                bf[nj * 2 + 0][0] = q[0]; bf[nj * 2 + 0][1] = q[2];
                bf[nj * 2 + 1][0] = q[1]; bf[nj * 2 + 1][1] = q[3];
            }
#pragma unroll
            for (int mi = 0; mi < 2; mi++)
#pragma unroll
                for (int ni = 0; ni < 8; ni++)
                    mma16(acc[mi][ni], af[mi], bf[ni]);
        }
        __syncthreads();
    }

#pragma unroll
    for (int mi = 0; mi < 2; mi++) {
#pragma unroll
        for (int r = 0; r < 2; r++) {
            const int gm = row0 + wm + mi * 16 + g + r * 8;
            if (gm >= M) continue;
            const float* rp = res + (size_t)gm * N;
#pragma unroll
            for (int ni = 0; ni < 8; ni++) {
                const int gn = col0 + wn + ni * 8 + 2 * t;
                float v0 = acc[mi][ni][r * 2 + 0] + bias[gn];
                float v1 = acc[mi][ni][r * 2 + 1] + bias[gn + 1];
                if (epi == 1) {
                    v0 += rp[gn];
                    v1 += rp[gn + 1];
                } else if (epi == 2) {
                    v0 = 0.5f * v0 * (1.0f + erff(v0 * 0.7071067811865475f));
                    v1 = 0.5f * v1 * (1.0f + erff(v1 * 0.7071067811865475f));
                }
                if (outHalf) {
                    *(__half2*)((__half*)outp + (size_t)gm * N + gn) = __floats2half2_rn(v0, v1);
                } else {
                    *(float2*)((float*)outp + (size_t)gm * N + gn) = make_float2(v0, v1);
                }
            }
        }
    }
}

// ============================================================================
// SMALL GEMM: BM=64, BN=128, BK=64, 128 threads (R7-proven); epi3 = LN fusion.
// ============================================================================
#define STG 24576
#define SREDOFF 49152
#define GEMM_SMEM 50176

__device__ __forceinline__ void gemm_load_stage(
    const __half* __restrict__ A, const __half* __restrict__ W, uint32_t sb,
    int st, int kt, int row0, int col0, int M, int K, int tid)
{
    const int r0 = tid >> 3, ck = tid & 7;
    const uint32_t base = sb + st * STG;
#pragma unroll
    for (int i = 0; i < 4; i++) {
        int r = r0 + i * 16;
        uint32_t swoff = (uint32_t)(r * 128 + ((ck ^ (r & 7)) * 16));
        int gm = row0 + r;
        cpa16(base + swoff, A + (size_t)gm * K + (size_t)kt * 64 + ck * 8, gm < M);
    }
#pragma unroll
    for (int i = 0; i < 8; i++) {
        int r = r0 + i * 16;
        uint32_t swoff = (uint32_t)(r * 128 + ((ck ^ (r & 7)) * 16));
        cpa16(base + 8192 + swoff,
              W + (size_t)(col0 + r) * K + (size_t)kt * 64 + ck * 8, true);
    }
}

__global__ __launch_bounds__(128, 4) void k_gemm_h(
    const __half* __restrict__ A, const __half* __restrict__ W,
    const float* __restrict__ bias, const float* __restrict__ res,
    void* __restrict__ outp, int M, int N, int K, int epi, int outHalf, int perm,
    const float* __restrict__ lnG, const float* __restrict__ lnB,
    __half* __restrict__ out2)
{
    extern __shared__ __align__(1024) char sm[];
    uint32_t sb = (uint32_t)__cvta_generic_to_shared(sm);
    float* sred = (float*)(sm + SREDOFF);
    const int tid = threadIdx.x, lane = tid & 31, warp = tid >> 5;
    const int g = lane >> 2, t = lane & 3;
    const int wm = (warp >> 1) * 32, wn = (warp & 1) * 64;
    const int row0 = blockIdx.y * 64, col0 = blockIdx.x * 128;
    const int KT = K >> 6;

    float acc[2][8][4];
#pragma unroll
    for (int mi = 0; mi < 2; mi++)
#pragma unroll
        for (int ni = 0; ni < 8; ni++)
#pragma unroll
            for (int r = 0; r < 4; r++) acc[mi][ni][r] = 0.f;

    gemm_load_stage(A, W, sb, 0, 0, row0, col0, M, K, tid);
    CP_COMMIT();

    for (int kt = 0; kt < KT; kt++) {
        const int s = kt & 1;
        if (kt + 1 < KT) {
            gemm_load_stage(A, W, sb, s ^ 1, kt + 1, row0, col0, M, K, tid);
            CP_COMMIT();
            CP_WAIT(1);
        } else {
            CP_WAIT(0);
        }
        __syncthreads();

        const uint32_t aS = sb + s * STG;
        const uint32_t bS = aS + 8192;
        const int rlow = lane & 15, hi = lane >> 4;
#pragma unroll
        for (int kk = 0; kk < 4; kk++) {
            uint32_t af[2][4];
#pragma unroll
            for (int mi = 0; mi < 2; mi++) {
                int r = wm + mi * 16 + rlow;
                int ck = kk * 2 + hi;
                ldm4(af[mi], aS + (uint32_t)(r * 128 + ((ck ^ (r & 7)) * 16)));
            }
            uint32_t bf[8][2];
#pragma unroll
            for (int nj = 0; nj < 4; nj++) {
                int r = wn + nj * 16 + rlow;
                int ck = kk * 2 + hi;
                uint32_t q[4];
                ldm4(q, bS + (uint32_t)(r * 128 + ((ck ^ (r & 7)) * 16)));
                bf[nj * 2 + 0][0] = q[0]; bf[nj * 2 + 0][1] = q[2];
                bf[nj * 2 + 1][0] = q[1]; bf[nj * 2 + 1][1] = q[3];
            }
#pragma unroll
            for (int mi = 0; mi < 2; mi++)
#pragma unroll
                for (int ni = 0; ni < 8; ni++)
                    mma16(acc[mi][ni], af[mi], bf[ni]);
        }
        __syncthreads();
    }

#pragma unroll
    for (int mi = 0; mi < 2; mi++) {
#pragma unroll
        for (int r = 0; r < 2; r++) {
            const int gm = row0 + wm + mi * 16 + g + r * 8;
            float psum = 0.f, psq = 0.f;
            if (gm < M) {
                const size_t orow = (epi == 3 && perm) ? (size_t)xcat_row(gm) : (size_t)gm;
                const float* rp = res + (size_t)gm * N;
#pragma unroll
                for (int ni = 0; ni < 8; ni++) {
                    const int gn = col0 + wn + ni * 8 + 2 * t;
                    float v0 = acc[mi][ni][r * 2 + 0] + bias[gn];
                    float v1 = acc[mi][ni][r * 2 + 1] + bias[gn + 1];
                    if (epi == 1 || epi == 3) {
                        v0 += rp[gn];
                        v1 += rp[gn + 1];
                    } else if (epi == 2) {
                        v0 = 0.5f * v0 * (1.0f + erff(v0 * 0.7071067811865475f));
                        v1 = 0.5f * v1 * (1.0f + erff(v1 * 0.7071067811865475f));
                    }
                    if (outHalf) {
                        *(__half2*)((__half*)outp + orow * N + gn) = __floats2half2_rn(v0, v1);
                    } else {
                        *(float2*)((float*)outp + orow * N + gn) = make_float2(v0, v1);
                    }
                    acc[mi][ni][r * 2 + 0] = v0;
                    acc[mi][ni][r * 2 + 1] = v1;
                    psum += v0 + v1;
                    psq  += v0 * v0 + v1 * v1;
                }
            }
            if (epi == 3) {
                psum += __shfl_xor_sync(0xffffffffu, psum, 1);
                psum += __shfl_xor_sync(0xffffffffu, psum, 2);
                psq  += __shfl_xor_sync(0xffffffffu, psq, 1);
                psq  += __shfl_xor_sync(0xffffffffu, psq, 2);
                if (t == 0) {
                    int lr = wm + mi * 16 + g + r * 8;
                    sred[lr * 4 + (warp & 1) * 2 + 0] = psum;
                    sred[lr * 4 + (warp & 1) * 2 + 1] = psq;
                }
            }
        }
    }
    if (epi == 3) {
        __syncthreads();
#pragma unroll
        for (int mi = 0; mi < 2; mi++) {
#pragma unroll
            for (int r = 0; r < 2; r++) {
                const int gm = row0 + wm + mi * 16 + g + r * 8;
                if (gm >= M) continue;
                const size_t orow = perm ? (size_t)xcat_row(gm) : (size_t)gm;
                const int lr = wm + mi * 16 + g + r * 8;
                float sum = sred[lr * 4 + 0] + sred[lr * 4 + 2];
                float sq  = sred[lr * 4 + 1] + sred[lr * 4 + 3];
                float mean = sum * (1.f / 128.f);
                float var = sq * (1.f / 128.f) - mean * mean;
                float rstd = rsqrtf(var + 1e-5f);
#pragma unroll
                for (int ni = 0; ni < 8; ni++) {
                    const int gn = col0 + wn + ni * 8 + 2 * t;
                    float a0 = (acc[mi][ni][r * 2 + 0] - mean) * rstd * lnG[gn] + lnB[gn];
                    float a1 = (acc[mi][ni][r * 2 + 1] - mean) * rstd * lnG[gn + 1] + lnB[gn + 1];
                    *(__half2*)(out2 + orow * 128 + gn) = __floats2half2_rn(a0, a1);
                }
            }
        }
    }
}

// ---------------- weight conversion + bias pack ----------------------------
__global__ void k_cvt_w(const float* __restrict__ w0, const float* __restrict__ w1,
                        const float* __restrict__ w2, const float* __restrict__ w3,
                        const float* __restrict__ w4, const float* __restrict__ w5,
                        const float* __restrict__ w6, const float* __restrict__ w7,
                        const float* __restrict__ b_off, const float* __restrict__ b_attn)
{
    if (blockIdx.x == 0 && threadIdx.x < 384)
        g_Bcat[threadIdx.x] = threadIdx.x < 256 ? b_off[threadIdx.x] : b_attn[threadIdx.x - 256];
    for (int idx = blockIdx.x * blockDim.x + threadIdx.x; idx < WTOTAL;
         idx += gridDim.x * blockDim.x) {
        const float* src; int off;
        if      (idx < WOFF_ATTN) { src = w0; off = idx; }
        else if (idx < WOFF_VAL ) { src = w1; off = idx - WOFF_ATTN; }
        else if (idx < WOFF_OUT ) { src = w2; off = idx - WOFF_VAL; }
        else if (idx < WOFF_IN  ) { src = w3; off = idx - WOFF_OUT; }
        else if (idx < WOFF_OUTW) { src = w4; off = idx - WOFF_IN; }
        else if (idx < WOFF_FC1 ) { src = w5; off = idx - WOFF_OUTW; }
        else if (idx < WOFF_FC2 ) { src = w6; off = idx - WOFF_FC1; }
        else                      { src = w7; off = idx - WOFF_FC2; }
        g_Wh[idx] = __float2half_rn(src[off]);
    }
}

// ---------------- LN1 + positional embedding -------------------------------
__global__ void k_ln1(const float* __restrict__ x, const float* __restrict__ pe,
                      const float* __restrict__ lp, const float* __restrict__ g,
                      const float* __restrict__ be)
{
    int row = blockIdx.x;
    int b = row / LQ; int lq = row - b * LQ;
    int l = lq & 3; int tp = lq >> 2; int p = tp % PP; int t = tp / PP;
    int c = threadIdx.x;
    size_t xi = ((((size_t)((b * TT + t) * PP + p)) * (LL + 1)) + (l + 1)) * CC + c;
    float v = x[xi];
    g_XS[(size_t)row * CC + c] = v;

    __shared__ float sh[8];
    float s = v;
    for (int o = 16; o > 0; o >>= 1) s += __shfl_xor_sync(0xffffffffu, s, o);
    if ((c & 31) == 0) sh[c >> 5] = s;
    __syncthreads();
    float mean = (sh[0] + sh[1] + sh[2] + sh[3]) * (1.f / CC);
    float dv = v - mean;
    float q2 = dv * dv;
    for (int o = 16; o > 0; o >>= 1) q2 += __shfl_xor_sync(0xffffffffu, q2, o);
    if ((c & 31) == 0) sh[4 + (c >> 5)] = q2;
    __syncthreads();
    float var = (sh[4] + sh[5] + sh[6] + sh[7]) * (1.f / CC);
    float xn = dv * rsqrtf(var + 1e-5f) * g[c] + be[c];
    g_XNh[(size_t)row * CC + c] = __float2half_rn(xn);
    g_Qh [(size_t)row * CC + c] = __float2half_rn(xn + pe[(size_t)lq * CC + c] + lp[(size_t)lq * CC + c]);
}

// ---------------- deformable sampling: 16 threads/row, 16B gathers ---------
#define DEF_RPB 8
__device__ __forceinline__ void ld8h(float* dst, const __half* p, bool valid) {
    if (valid) {
        uint4 q = *(const uint4*)p;
        const __half2* hp = (const __half2*)&q;
#pragma unroll
        for (int j = 0; j < 4; j++) {
            float2 f = __half22float2(hp[j]);
            dst[2 * j] = f.x; dst[2 * j + 1] = f.y;
        }
    } else {
#pragma unroll
        for (int j = 0; j < 8; j++) dst[j] = 0.f;
    }
}

__global__ __launch_bounds__(128) void k_deform(const float* __restrict__ refp)
{
    __shared__ float sOFF[DEF_RPB][384];
    const int row0 = blockIdx.x * DEF_RPB;
    const int tid = threadIdx.x;

    for (int idx = tid; idx < DEF_RPB * 192; idx += 128) {
        int rr = idx / 192, c2 = idx - rr * 192;
        float2 v = __half22float2(*(const __half2*)(g_OFFAWh + (size_t)(row0 + rr) * 384 + c2 * 2));
        sOFF[rr][c2 * 2 + 0] = v.x;
        sOFF[rr][c2 * 2 + 1] = v.y;
    }
    __syncthreads();

    const int rr = tid >> 4;
    const int s = tid & 15;
    const int row = row0 + rr;
    const int b = row / LQ; const int lq = row - b * LQ;
    const int tp = lq >> 2; const int p = tp % PP; const int t = tp / PP;
    const int h = s >> 1, dq = s & 1;
    const float refx = refp[(((size_t)b * TT + t) * PP + p) * 2 + 0];
    const float refy = refp[(((size_t)b * TT + t) * PP + p) * 2 + 1];

    const float* awp = &sOFF[rr][256 + h * 16];
    float w[16], mx = -1e30f;
#pragma unroll
    for (int i = 0; i < 16; i++) { w[i] = awp[i]; mx = fmaxf(mx, w[i]); }
    float den = 0.f;
#pragma unroll
    for (int i = 0; i < 16; i++) { w[i] = expf(w[i] - mx); den += w[i]; }
    float inv = 1.f / den;

    const float*  offp  = &sOFF[rr][h * 32];
    const __half* vbase = g_VALh + (size_t)b * LQ * CC + h * 16 + dq * 8;
    float acc[8];
#pragma unroll
    for (int j = 0; j < 8; j++) acc[j] = 0.f;

#pragma unroll
    for (int l = 0; l < LL; l++) {
#pragma unroll
        for (int pt = 0; pt < NPT; pt++) {
            float ox = offp[(l * 4 + pt) * 2 + 0];
            float oy = offp[(l * 4 + pt) * 2 + 1];
            float fx = refx * PP + ox - 0.5f;
            float fy = refy * TT + oy - 0.5f;
            float x0f = floorf(fx), y0f = floorf(fy);
            int x0 = (int)x0f, y0 = (int)y0f;
            float wx1 = fx - x0f, wy1 = fy - y0f;
            float wx0 = 1.f - wx1, wy0 = 1.f - wy1;
            bool xi0 = (x0 >= 0) && (x0 < PP);
            bool xi1 = (x0 + 1 >= 0) && (x0 + 1 < PP);
            bool yi0 = (y0 >= 0) && (y0 < TT);
            bool yi1 = (y0 + 1 >= 0) && (y0 + 1 < TT);
            float v00[8], v01[8], v10[8], v11[8];
            ld8h(v00, vbase + ((size_t)(y0 * PP + x0) * LL + l) * CC,           yi0 && xi0);
            ld8h(v01, vbase + ((size_t)(y0 * PP + x0 + 1) * LL + l) * CC,       yi0 && xi1);
            ld8h(v10, vbase + ((size_t)((y0 + 1) * PP + x0) * LL + l) * CC,     yi1 && xi0);
            ld8h(v11, vbase + ((size_t)((y0 + 1) * PP + x0 + 1) * LL + l) * CC, yi1 && xi1);
            float w00 = wy0 * wx0, w01 = wy0 * wx1, w10 = wy1 * wx0, w11 = wy1 * wx1;
            float ww = w[l * 4 + pt];
#pragma unroll
            for (int j = 0; j < 8; j++) {
                float sv = v00[j] * w00 + v01[j] * w01 + v10[j] * w10 + v11[j] * w11;
                acc[j] = fmaf(sv, ww, acc[j]);
            }
        }
    }
    __half2 ho[4];
#pragma unroll
    for (int j = 0; j < 4; j++)
        ho[j] = __floats2half2_rn(acc[2 * j] * inv, acc[2 * j + 1] * inv);
    *(uint4*)(g_Oh + (size_t)row * CC + h * 16 + dq * 8) = *(uint4*)ho;
}

// ---------------- level-0 rows: copy x + LN2 -------------------------------
__global__ void k_lvl0(const float* __restrict__ x, const float* __restrict__ g,
                       const float* __restrict__ be)
{
    int btp = blockIdx.x;
    int c = threadIdx.x;
    size_t rowoff = (size_t)btp * NLVL * CC;
    float v = x[rowoff + c];
    g_XCAT[rowoff + c] = v;

    __shared__ float sh[8];
    float s = v;
    for (int o = 16; o > 0; o >>= 1) s += __shfl_xor_sync(0xffffffffu, s, o);
    if ((c & 31) == 0) sh[c >> 5] = s;
    __syncthreads();
    float mean = (sh[0] + sh[1] + sh[2] + sh[3]) * (1.f / CC);
    float dv = v - mean;
    float q2 = dv * dv;
    for (int o = 16; o > 0; o >>= 1) q2 += __shfl_xor_sync(0xffffffffu, q2, o);
    if ((c & 31) == 0) sh[4 + (c >> 5)] = q2;
    __syncthreads();
    float var = (sh[4] + sh[5] + sh[6] + sh[7]) * (1.f / CC);
    g_XN2h[rowoff + c] = __float2half_rn(dv * rsqrtf(var + 1e-5f) * g[c] + be[c]);
}

// ---------------- per-(bt,head) self-attention (fp16 QKV) ------------------
__global__ void k_attn()
{
    int bt = blockIdx.x, h = blockIdx.y;
    __shared__ float Qs[SS][DHH], Ks[SS][DHH], Vs[SS][DHH];
    int tid = threadIdx.x;
    for (int i = tid; i < SS * DHH; i += 128) {
        int s = i >> 4, d = i & 15;
        const __half* base = g_QKVh + ((size_t)bt * SS + s) * 384 + h * 16 + d;
        Qs[s][d] = __half2float(base[0]);
        Ks[s][d] = __half2float(base[128]);
        Vs[s][d] = __half2float(base[256]);
    }
    __syncthreads();
    if (tid < SS) {
        float qv[16];
#pragma unroll
        for (int d = 0; d < 16; d++) qv[d] = Qs[tid][d];
        float mx = -1e30f;
        for (int k = 0; k < SS; k++) {
            float sdot = 0.f;
#pragma unroll
            for (int d = 0; d < 16; d++) sdot = fmaf(qv[d], Ks[k][d], sdot);
            mx = fmaxf(mx, sdot * 0.25f);
        }
        float den = 0.f, o[16];
#pragma unroll
        for (int d = 0; d < 16; d++) o[d] = 0.f;
        for (int k = 0; k < SS; k++) {
            float sdot = 0.f;
#pragma unroll
            for (int d = 0; d < 16; d++) sdot = fmaf(qv[d], Ks[k][d], sdot);
            float e = expf(sdot * 0.25f - mx);
            den += e;
#pragma unroll
            for (int d = 0; d < 16; d++) o[d] = fmaf(e, Vs[k][d], o[d]);
        }
        float inv = 1.f / den;
        __half* outp = g_ATTOh + ((size_t)bt * SS + tid) * CC + h * 16;
#pragma unroll
        for (int d = 0; d < 16; d++) outp[d] = __float2half_rn(o[d] * inv);
    }
}

// ---------------- host launch ----------------------------------------------
static inline void launch_small(const __half* A, const __half* W, const float* bias,
                                const float* res, void* out, int M, int N, int K,
                                int epi, int outHalf, int perm = 0,
                                const float* lnG = nullptr, const float* lnB = nullptr,
                                __half* out2 = nullptr)
{
    dim3 grid(N / 128, (M + 63) / 64);
    k_gemm_h<<<grid, 128, GEMM_SMEM>>>(A, W, bias, res ? res : (const float*)A,
                                       out, M, N, K, epi, outHalf, perm, lnG, lnB, out2);
}
static inline void launch_big(const __half* A, const __half* W, const float* bias,
                              const float* res, void* out, int M, int N, int K,
                              int epi, int outHalf)
{
    dim3 grid(N / 128, (M + 127) / 128);
    k_gemm_big<<<grid, 256, BIG_SMEM>>>(A, W, bias, res ? res : (const float*)A,
                                        out, M, N, K, epi, outHalf);
}

extern "C" void kernel_launch(void* const* d_in, const int* in_sizes, int n_in,
                              void* d_out, int out_size)
{
    (void)in_sizes; (void)n_in; (void)out_size;
    const float* x        = (const float*)d_in[0];
    const float* refp     = (const float*)d_in[1];
    const float* pe_buf   = (const float*)d_in[2];
    const float* learn_pos= (const float*)d_in[3];
    const float* w_off    = (const float*)d_in[4];
    const float* b_off    = (const float*)d_in[5];
    const float* w_attn   = (const float*)d_in[6];
    const float* b_attn   = (const float*)d_in[7];
    const float* w_val    = (const float*)d_in[8];
    const float* b_val    = (const float*)d_in[9];
    const float* w_out    = (const float*)d_in[10];
    const float* b_out    = (const float*)d_in[11];
    const float* in_w     = (const float*)d_in[12];
    const float* in_b     = (const float*)d_in[13];
    const float* out_w    = (const float*)d_in[14];
    const float* b_out2   = (const float*)d_in[15];
    const float* fc1_w    = (const float*)d_in[16];
    const float* fc1_b    = (const float*)d_in[17];
    const float* fc2_w    = (const float*)d_in[18];
    const float* fc2_b    = (const float*)d_in[19];
    const float* g1       = (const float*)d_in[20];
    const float* be1      = (const float*)d_in[21];
    const float* g2       = (const float*)d_in[22];
    const float* be2      = (const float*)d_in[23];
    const float* g3       = (const float*)d_in[24];
    const float* be3      = (const float*)d_in[25];
    float* out = (float*)d_out;

    cudaFuncSetAttribute(k_gemm_h,   cudaFuncAttributeMaxDynamicSharedMemorySize, GEMM_SMEM);
    cudaFuncSetAttribute(k_gemm_big, cudaFuncAttributeMaxDynamicSharedMemorySize, BIG_SMEM);

    float *pXS, *pXCAT, *pXCAT2, *pBcat;
    __half *pOFFAWh, *pQh, *pXNh, *pVALh, *pOh, *pXN2h, *pQKVh, *pATTOh, *pXN3h, *pHIDh, *pWh;
    cudaGetSymbolAddress((void**)&pXS,    g_XS);
    cudaGetSymbolAddress((void**)&pXCAT,  g_XCAT);
    cudaGetSymbolAddress((void**)&pXCAT2, g_XCAT2);
    cudaGetSymbolAddress((void**)&pBcat,  g_Bcat);
    cudaGetSymbolAddress((void**)&pOFFAWh,g_OFFAWh);
    cudaGetSymbolAddress((void**)&pQh,    g_Qh);
    cudaGetSymbolAddress((void**)&pXNh,   g_XNh);
    cudaGetSymbolAddress((void**)&pVALh,  g_VALh);
    cudaGetSymbolAddress((void**)&pOh,    g_Oh);
    cudaGetSymbolAddress((void**)&pXN2h,  g_XN2h);
    cudaGetSymbolAddress((void**)&pQKVh,  g_QKVh);
    cudaGetSymbolAddress((void**)&pATTOh, g_ATTOh);
    cudaGetSymbolAddress((void**)&pXN3h,  g_XN3h);
    cudaGetSymbolAddress((void**)&pHIDh,  g_HIDh);
    cudaGetSymbolAddress((void**)&pWh,    g_Wh);

    // 0) weight conversion + bias pack
    k_cvt_w<<<272, 256>>>(w_off, w_attn, w_val, w_out, in_w, out_w, fc1_w, fc2_w,
                          b_off, b_attn);
    // 1) LN1 + pos-embed
    k_ln1<<<BLQ, 128>>>(x, pe_buf, learn_pos, g1, be1);
    // 1b) level-0 rows of xcat + LN2
    k_lvl0<<<BTP, 128>>>(x, g2, be2);
    // 2) fused offsets+attnw GEMM (N=384) -> fp16   [BIG]
    launch_big(pQh,  pWh + WOFF_OFF,  pBcat,  nullptr, pOFFAWh, BLQ, 384, CC, 0, 1);
    // 3) value GEMM (N=128) -> fp16                 [small]
    launch_small(pXNh, pWh + WOFF_VAL, b_val, nullptr, pVALh,   BLQ, 128, CC, 0, 1);
    // 4) deformable sampling
    k_deform<<<BLQ / DEF_RPB, 128>>>(refp);
    // 5) out-proj + residual + concat-permute + fused LN2  [small, epi3]
    launch_small(pOh,  pWh + WOFF_OUT, b_out, pXS,     pXCAT,   BLQ, 128, CC, 3, 0, 1,
                 g2, be2, pXN2h);
    // 7) QKV GEMM (N=384) -> fp16                   [BIG]
    launch_big(pXN2h, pWh + WOFF_IN,  in_b,   nullptr, pQKVh,   TOK, 384, CC, 0, 1);
    // 8) self-attention
    k_attn<<<dim3(BB * TT, HH), 128>>>();
    // 9) attention out-proj + residual + fused LN3  [small, epi3]
    launch_small(pATTOh, pWh + WOFF_OUTW, b_out2, pXCAT, pXCAT2, TOK, 128, CC, 3, 0, 0,
                 g3, be3, pXN3h);
    // 10) FC1 + GELU (N=512) -> fp16                [BIG]
    launch_big(pXN3h, pWh + WOFF_FC1, fc1_b,  nullptr, pHIDh,   TOK, 512, CC, 2, 1);
    // 11) FC2 + residual -> final output (K=512)    [BIG]
    launch_big(pHIDh, pWh + WOFF_FC2, fc2_b,  pXCAT2, out,     TOK, 128, 512, 1, 0);
}

// round 11
// speedup vs baseline: 1.0286x; 1.0286x over previous
#include <cuda_runtime.h>
#include <cuda_fp16.h>
#include <math.h>
#include <stdint.h>

// Problem constants
#define TT   243
#define PP   17
#define LL   4
#define CC   128
#define HH   8
#define NPT  4
#define DHH  16
#define BB   2
#define LQ   (TT*PP*LL)        // 16524
#define BLQ  (BB*LQ)           // 33048
#define NLVL 5
#define BTP  (BB*TT*PP)        // 8262
#define TOK  (BTP*NLVL)        // 41310
#define SS   (PP*NLVL)         // 85

// ---------------- scratch (device globals; no allocations) ----------------
__device__ float  g_XCAT [(size_t)TOK*CC];
__device__ float  g_XCAT2[(size_t)TOK*CC];
__device__ __half g_OFFAWh[(size_t)BLQ*384];
__device__ __half g_Qh   [(size_t)BLQ*CC];
__device__ __half g_XNh  [(size_t)BLQ*CC];
__device__ __half g_VALh [(size_t)BLQ*CC];
__device__ __half g_Oh   [(size_t)BLQ*CC];
__device__ __half g_XN2h [(size_t)TOK*CC];
__device__ __half g_QKVh [(size_t)TOK*384];
__device__ __half g_ATTOh[(size_t)TOK*CC];
__device__ __half g_XN3h [(size_t)TOK*CC];
__device__ __half g_HIDh [(size_t)TOK*512];
#define WOFF_OFF   0
#define WOFF_ATTN  32768
#define WOFF_VAL   49152
#define WOFF_OUT   65536
#define WOFF_IN    81920
#define WOFF_OUTW  131072
#define WOFF_FC1   147456
#define WOFF_FC2   212992
#define WTOTAL     278528
__device__ __half g_Wh[WTOTAL];
__device__ float  g_Bcat[384];

// ---------------- PTX helpers ----------------------------------------------
__device__ __forceinline__ void cpa16(uint32_t dst, const void* src, bool valid) {
    int sz = valid ? 16 : 0;
    asm volatile("cp.async.cg.shared.global [%0], [%1], 16, %2;\n"
                 :: "r"(dst), "l"(src), "r"(sz));
}
#define CP_COMMIT() asm volatile("cp.async.commit_group;\n" ::: "memory")
#define CP_WAIT(n)  asm volatile("cp.async.wait_group %0;\n" :: "n"(n) : "memory")

__device__ __forceinline__ void ldm4(uint32_t* r, uint32_t addr) {
    asm volatile("ldmatrix.sync.aligned.m8n8.x4.shared.b16 {%0,%1,%2,%3}, [%4];\n"
                 : "=r"(r[0]), "=r"(r[1]), "=r"(r[2]), "=r"(r[3]) : "r"(addr));
}
__device__ __forceinline__ void mma16(float* c, const uint32_t* a, const uint32_t* b) {
    asm volatile("mma.sync.aligned.m16n8k16.row.col.f32.f16.f16.f32 "
                 "{%0,%1,%2,%3},{%4,%5,%6,%7},{%8,%9},{%0,%1,%2,%3};\n"
                 : "+f"(c[0]), "+f"(c[1]), "+f"(c[2]), "+f"(c[3])
                 : "r"(a[0]), "r"(a[1]), "r"(a[2]), "r"(a[3]), "r"(b[0]), "r"(b[1]));
}

// permuted destination row for the xcat concat (also the x source row!)
__device__ __forceinline__ int xcat_row(int gm) {
    int b = gm / LQ;
    int rem = gm - b * LQ;
    return (b * (TT * PP) + (rem >> 2)) * 5 + (rem & 3) + 1;
}

// ============================================================================
// BIG GEMM: BM=128, BN=128, BK=64, 256 threads (QKV / FC1 / FC2).
// ============================================================================
#define BIG_STG  32768
#define BIG_SMEM 65536

__device__ __forceinline__ void big_load_stage(
    const __half* __restrict__ A, const __half* __restrict__ W, uint32_t sb,
    int st, int kt, int row0, int col0, int M, int K, int tid)
{
    const int r0 = tid >> 3, ck = tid & 7;
    const uint32_t base = sb + st * BIG_STG;
#pragma unroll
    for (int i = 0; i < 4; i++) {
        int r = r0 + i * 32;
        uint32_t swoff = (uint32_t)(r * 128 + ((ck ^ (r & 7)) * 16));
        int gm = row0 + r;
        cpa16(base + swoff, A + (size_t)gm * K + (size_t)kt * 64 + ck * 8, gm < M);
        cpa16(base + 16384 + swoff,
              W + (size_t)(col0 + r) * K + (size_t)kt * 64 + ck * 8, true);
    }
}

__global__ __launch_bounds__(256, 2) void k_gemm_big(
    const __half* __restrict__ A, const __half* __restrict__ W,
    const float* __restrict__ bias, const float* __restrict__ res,
    void* __restrict__ outp, int M, int N, int K, int epi, int outHalf)
{
    extern __shared__ __align__(1024) char sm[];
    uint32_t sb = (uint32_t)__cvta_generic_to_shared(sm);
    const int tid = threadIdx.x, lane = tid & 31, warp = tid >> 5;
    const int g = lane >> 2, t = lane & 3;
    const int wm = (warp >> 1) * 32, wn = (warp & 1) * 64;
    const int row0 = blockIdx.y * 128, col0 = blockIdx.x * 128;
    const int KT = K >> 6;

    float acc[2][8][4];
#pragma unroll
    for (int mi = 0; mi < 2; mi++)
#pragma unroll
        for (int ni = 0; ni < 8; ni++)
#pragma unroll
            for (int r = 0; r < 4; r++) acc[mi][ni][r] = 0.f;

    big_load_stage(A, W, sb, 0, 0, row0, col0, M, K, tid);
    CP_COMMIT();

    for (int kt = 0; kt < KT; kt++) {
        const int s = kt & 1;
        if (kt + 1 < KT) {
            big_load_stage(A, W, sb, s ^ 1, kt + 1, row0, col0, M, K, tid);
            CP_COMMIT();
            CP_WAIT(1);
        } else {
            CP_WAIT(0);
        }
        __syncthreads();

        const uint32_t aS = sb + s * BIG_STG;
        const uint32_t bS = aS + 16384;
        const int rlow = lane & 15, hi = lane >> 4;
#pragma unroll
        for (int kk = 0; kk < 4; kk++) {
            uint32_t af[2][4];
#pragma unroll
            for (int mi = 0; mi < 2; mi++) {
                int r = wm + mi * 16 + rlow;
                int ck = kk * 2 + hi;
                ldm4(af[mi], aS + (uint32_t)(r * 128 + ((ck ^ (r & 7)) * 16)));
            }
            uint32_t bf[8][2];
#pragma unroll
            for (int nj = 0; nj < 4; nj++) {
                int r = wn + nj * 16 + rlow;
                int ck = kk * 2 + hi;
                uint32_t q[4];
                ldm4(q, bS + (uint32_t)(r * 128 + ((ck ^ (r & 7)) * 16)));
                bf[nj * 2 + 0][0] = q[0]; bf[nj * 2 + 0][1] = q[2];
                bf[nj * 2 + 1][0] = q[1]; bf[nj * 2 + 1][1] = q[3];
            }
#pragma unroll
            for (int mi = 0; mi < 2; mi++)
#pragma unroll
                for (int ni = 0; ni < 8; ni++)
                    mma16(acc[mi][ni], af[mi], bf[ni]);
        }
        __syncthreads();
    }

#pragma unroll
    for (int mi = 0; mi < 2; mi++) {
#pragma unroll
        for (int r = 0; r < 2; r++) {
            const int gm = row0 + wm + mi * 16 + g + r * 8;
            if (gm >= M) continue;
            const float* rp = res + (size_t)gm * N;
#pragma unroll
            for (int ni = 0; ni < 8; ni++) {
                const int gn = col0 + wn + ni * 8 + 2 * t;
                float v0 = acc[mi][ni][r * 2 + 0] + bias[gn];
                float v1 = acc[mi][ni][r * 2 + 1] + bias[gn + 1];
                if (epi == 1) {
                    v0 += rp[gn];
                    v1 += rp[gn + 1];
                } else if (epi == 2) {
                    v0 = 0.5f * v0 * (1.0f + erff(v0 * 0.7071067811865475f));
                    v1 = 0.5f * v1 * (1.0f + erff(v1 * 0.7071067811865475f));
                }
                if (outHalf) {
                    *(__half2*)((__half*)outp + (size_t)gm * N + gn) = __floats2half2_rn(v0, v1);
                } else {
                    *(float2*)((float*)outp + (size_t)gm * N + gn) = make_float2(v0, v1);
                }
            }
        }
    }
}

// ============================================================================
// SMALL GEMM: BM=64, BN=128, BK=64, 128 threads; epi3 = residual + LN fusion.
// For epi3+perm the residual source rows are indexed by xcat_row (res = x).
// ============================================================================
#define STG 24576
#define SREDOFF 49152
#define GEMM_SMEM 50176

__device__ __forceinline__ void gemm_load_stage(
    const __half* __restrict__ A, const __half* __restrict__ W, uint32_t sb,
    int st, int kt, int row0, int col0, int M, int K, int tid)
{
    const int r0 = tid >> 3, ck = tid & 7;
    const uint32_t base = sb + st * STG;
#pragma unroll
    for (int i = 0; i < 4; i++) {
        int r = r0 + i * 16;
        uint32_t swoff = (uint32_t)(r * 128 + ((ck ^ (r & 7)) * 16));
        int gm = row0 + r;
        cpa16(base + swoff, A + (size_t)gm * K + (size_t)kt * 64 + ck * 8, gm < M);
    }
#pragma unroll
    for (int i = 0; i < 8; i++) {
        int r = r0 + i * 16;
        uint32_t swoff = (uint32_t)(r * 128 + ((ck ^ (r & 7)) * 16));
        cpa16(base + 8192 + swoff,
              W + (size_t)(col0 + r) * K + (size_t)kt * 64 + ck * 8, true);
    }
}

__global__ __launch_bounds__(128, 4) void k_gemm_h(
    const __half* __restrict__ A, const __half* __restrict__ W,
    const float* __restrict__ bias, const float* __restrict__ res,
    void* __restrict__ outp, int M, int N, int K, int epi, int outHalf, int perm,
    const float* __restrict__ lnG, const float* __restrict__ lnB,
    __half* __restrict__ out2)
{
    extern __shared__ __align__(1024) char sm[];
    uint32_t sb = (uint32_t)__cvta_generic_to_shared(sm);
    float* sred = (float*)(sm + SREDOFF);
    const int tid = threadIdx.x, lane = tid & 31, warp = tid >> 5;
    const int g = lane >> 2, t = lane & 3;
    const int wm = (warp >> 1) * 32, wn = (warp & 1) * 64;
    const int row0 = blockIdx.y * 64, col0 = blockIdx.x * 128;
    const int KT = K >> 6;

    float acc[2][8][4];
#pragma unroll
    for (int mi = 0; mi < 2; mi++)
#pragma unroll
        for (int ni = 0; ni < 8; ni++)
#pragma unroll
            for (int r = 0; r < 4; r++) acc[mi][ni][r] = 0.f;

    gemm_load_stage(A, W, sb, 0, 0, row0, col0, M, K, tid);
    CP_COMMIT();

    for (int kt = 0; kt < KT; kt++) {
        const int s = kt & 1;
        if (kt + 1 < KT) {
            gemm_load_stage(A, W, sb, s ^ 1, kt + 1, row0, col0, M, K, tid);
            CP_COMMIT();
            CP_WAIT(1);
        } else {
            CP_WAIT(0);
        }
        __syncthreads();

        const uint32_t aS = sb + s * STG;
        const uint32_t bS = aS + 8192;
        const int rlow = lane & 15, hi = lane >> 4;
#pragma unroll
        for (int kk = 0; kk < 4; kk++) {
            uint32_t af[2][4];
#pragma unroll
            for (int mi = 0; mi < 2; mi++) {
                int r = wm + mi * 16 + rlow;
                int ck = kk * 2 + hi;
                ldm4(af[mi], aS + (uint32_t)(r * 128 + ((ck ^ (r & 7)) * 16)));
            }
            uint32_t bf[8][2];
#pragma unroll
            for (int nj = 0; nj < 4; nj++) {
                int r = wn + nj * 16 + rlow;
                int ck = kk * 2 + hi;
                uint32_t q[4];
                ldm4(q, bS + (uint32_t)(r * 128 + ((ck ^ (r & 7)) * 16)));
                bf[nj * 2 + 0][0] = q[0]; bf[nj * 2 + 0][1] = q[2];
                bf[nj * 2 + 1][0] = q[1]; bf[nj * 2 + 1][1] = q[3];
            }
#pragma unroll
            for (int mi = 0; mi < 2; mi++)
#pragma unroll
                for (int ni = 0; ni < 8; ni++)
                    mma16(acc[mi][ni], af[mi], bf[ni]);
        }
        __syncthreads();
    }

#pragma unroll
    for (int mi = 0; mi < 2; mi++) {
#pragma unroll
        for (int r = 0; r < 2; r++) {
            const int gm = row0 + wm + mi * 16 + g + r * 8;
            float psum = 0.f, psq = 0.f;
            if (gm < M) {
                const size_t orow = (epi == 3 && perm) ? (size_t)xcat_row(gm) : (size_t)gm;
                const float* rp = res + orow * N;     // residual rows follow the perm too
#pragma unroll
                for (int ni = 0; ni < 8; ni++) {
                    const int gn = col0 + wn + ni * 8 + 2 * t;
                    float v0 = acc[mi][ni][r * 2 + 0] + bias[gn];
                    float v1 = acc[mi][ni][r * 2 + 1] + bias[gn + 1];
                    if (epi == 1 || epi == 3) {
                        v0 += rp[gn];
                        v1 += rp[gn + 1];
                    } else if (epi == 2) {
                        v0 = 0.5f * v0 * (1.0f + erff(v0 * 0.7071067811865475f));
                        v1 = 0.5f * v1 * (1.0f + erff(v1 * 0.7071067811865475f));
                    }
                    if (outHalf) {
                        *(__half2*)((__half*)outp + orow * N + gn) = __floats2half2_rn(v0, v1);
                    } else {
                        *(float2*)((float*)outp + orow * N + gn) = make_float2(v0, v1);
                    }
                    acc[mi][ni][r * 2 + 0] = v0;
                    acc[mi][ni][r * 2 + 1] = v1;
                    psum += v0 + v1;
                    psq  += v0 * v0 + v1 * v1;
                }
            }
            if (epi == 3) {
                psum += __shfl_xor_sync(0xffffffffu, psum, 1);
                psum += __shfl_xor_sync(0xffffffffu, psum, 2);
                psq  += __shfl_xor_sync(0xffffffffu, psq, 1);
                psq  += __shfl_xor_sync(0xffffffffu, psq, 2);
                if (t == 0) {
                    int lr = wm + mi * 16 + g + r * 8;
                    sred[lr * 4 + (warp & 1) * 2 + 0] = psum;
                    sred[lr * 4 + (warp & 1) * 2 + 1] = psq;
                }
            }
        }
    }
    if (epi == 3) {
        __syncthreads();
#pragma unroll
        for (int mi = 0; mi < 2; mi++) {
#pragma unroll
            for (int r = 0; r < 2; r++) {
                const int gm = row0 + wm + mi * 16 + g + r * 8;
                if (gm >= M) continue;
                const size_t orow = perm ? (size_t)xcat_row(gm) : (size_t)gm;
                const int lr = wm + mi * 16 + g + r * 8;
                float sum = sred[lr * 4 + 0] + sred[lr * 4 + 2];
                float sq  = sred[lr * 4 + 1] + sred[lr * 4 + 3];
                float mean = sum * (1.f / 128.f);
                float var = sq * (1.f / 128.f) - mean * mean;
                float rstd = rsqrtf(var + 1e-5f);
#pragma unroll
                for (int ni = 0; ni < 8; ni++) {
                    const int gn = col0 + wn + ni * 8 + 2 * t;
                    float a0 = (acc[mi][ni][r * 2 + 0] - mean) * rstd * lnG[gn] + lnB[gn];
                    float a1 = (acc[mi][ni][r * 2 + 1] - mean) * rstd * lnG[gn + 1] + lnB[gn + 1];
                    *(__half2*)(out2 + orow * 128 + gn) = __floats2half2_rn(a0, a1);
                }
            }
        }
    }
}

// ============================================================================
// Merged projection GEMM: offaw (N=384, cols 0-2) + val (N=128, col 3).
// ============================================================================
__global__ __launch_bounds__(128, 4) void k_projs(const float* __restrict__ b_val)
{
    extern __shared__ __align__(1024) char sm[];
    uint32_t sb = (uint32_t)__cvta_generic_to_shared(sm);
    const int tid = threadIdx.x, lane = tid & 31, warp = tid >> 5;
    const int g = lane >> 2, t = lane & 3;
    const int wm = (warp >> 1) * 32, wn = (warp & 1) * 64;
    const int row0 = blockIdx.y * 64;

    const __half* A; const __half* W; const float* bias; __half* outp; int N; int col0;
    if (blockIdx.x < 3) {
        A = g_Qh;  W = g_Wh + WOFF_OFF; bias = g_Bcat; outp = g_OFFAWh;
        N = 384; col0 = blockIdx.x * 128;
    } else {
        A = g_XNh; W = g_Wh + WOFF_VAL; bias = b_val;  outp = g_VALh;
        N = 128; col0 = 0;
    }
    const int M = BLQ, K = CC, KT = 2;

    float acc[2][8][4];
#pragma unroll
    for (int mi = 0; mi < 2; mi++)
#pragma unroll
        for (int ni = 0; ni < 8; ni++)
#pragma unroll
            for (int r = 0; r < 4; r++) acc[mi][ni][r] = 0.f;

    gemm_load_stage(A, W, sb, 0, 0, row0, col0, M, K, tid);
    CP_COMMIT();

    for (int kt = 0; kt < KT; kt++) {
        const int s = kt & 1;
        if (kt + 1 < KT) {
            gemm_load_stage(A, W, sb, s ^ 1, kt + 1, row0, col0, M, K, tid);
            CP_COMMIT();
            CP_WAIT(1);
        } else {
            CP_WAIT(0);
        }
        __syncthreads();

        const uint32_t aS = sb + s * STG;
        const uint32_t bS = aS + 8192;
        const int rlow = lane & 15, hi = lane >> 4;
#pragma unroll
        for (int kk = 0; kk < 4; kk++) {
            uint32_t af[2][4];
#pragma unroll
            for (int mi = 0; mi < 2; mi++) {
                int r = wm + mi * 16 + rlow;
                int ck = kk * 2 + hi;
                ldm4(af[mi], aS + (uint32_t)(r * 128 + ((ck ^ (r & 7)) * 16)));
            }
            uint32_t bf[8][2];
#pragma unroll
            for (int nj = 0; nj < 4; nj++) {
                int r = wn + nj * 16 + rlow;
                int ck = kk * 2 + hi;
                uint32_t q[4];
                ldm4(q, bS + (uint32_t)(r * 128 + ((ck ^ (r & 7)) * 16)));
                bf[nj * 2 + 0][0] = q[0]; bf[nj * 2 + 0][1] = q[2];
                bf[nj * 2 + 1][0] = q[1]; bf[nj * 2 + 1][1] = q[3];
            }
#pragma unroll
            for (int mi = 0; mi < 2; mi++)
#pragma unroll
                for (int ni = 0; ni < 8; ni++)
                    mma16(acc[mi][ni], af[mi], bf[ni]);
        }
        __syncthreads();
    }

#pragma unroll
    for (int mi = 0; mi < 2; mi++) {
#pragma unroll
        for (int r = 0; r < 2; r++) {
            const int gm = row0 + wm + mi * 16 + g + r * 8;
            if (gm >= M) continue;
#pragma unroll
            for (int ni = 0; ni < 8; ni++) {
                const int gn = col0 + wn + ni * 8 + 2 * t;
                float v0 = acc[mi][ni][r * 2 + 0] + bias[gn];
                float v1 = acc[mi][ni][r * 2 + 1] + bias[gn + 1];
                *(__half2*)(outp + (size_t)gm * N + gn) = __floats2half2_rn(v0, v1);
            }
        }
    }
}

// ============================================================================
// Merged prologue: ln1 (BLQ blocks) + lvl0 (BTP blocks) + weight cvt (272).
// ============================================================================
__global__ __launch_bounds__(128) void k_pre(
    const float* __restrict__ x, const float* __restrict__ pe,
    const float* __restrict__ lp,
    const float* __restrict__ g1, const float* __restrict__ be1,
    const float* __restrict__ g2, const float* __restrict__ be2,
    const float* __restrict__ w0, const float* __restrict__ w1,
    const float* __restrict__ w2, const float* __restrict__ w3,
    const float* __restrict__ w4, const float* __restrict__ w5,
    const float* __restrict__ w6, const float* __restrict__ w7,
    const float* __restrict__ b_off, const float* __restrict__ b_attn)
{
    const int bid = blockIdx.x;
    const int c = threadIdx.x;

    if (bid < BLQ) {
        // ---- LN1 + positional embedding ----
        int row = bid;
        int b = row / LQ; int lq = row - b * LQ;
        int l = lq & 3; int tp = lq >> 2;
        size_t xi = ((size_t)(b * TT * PP + tp) * NLVL + (l + 1)) * CC + c;
        float v = x[xi];

        __shared__ float sh[8];
        float s = v;
        for (int o = 16; o > 0; o >>= 1) s += __shfl_xor_sync(0xffffffffu, s, o);
        if ((c & 31) == 0) sh[c >> 5] = s;
        __syncthreads();
        float mean = (sh[0] + sh[1] + sh[2] + sh[3]) * (1.f / CC);
        float dv = v - mean;
        float q2 = dv * dv;
        for (int o = 16; o > 0; o >>= 1) q2 += __shfl_xor_sync(0xffffffffu, q2, o);
        if ((c & 31) == 0) sh[4 + (c >> 5)] = q2;
        __syncthreads();
        float var = (sh[4] + sh[5] + sh[6] + sh[7]) * (1.f / CC);
        float xn = dv * rsqrtf(var + 1e-5f) * g1[c] + be1[c];
        g_XNh[(size_t)row * CC + c] = __float2half_rn(xn);
        g_Qh [(size_t)row * CC + c] = __float2half_rn(xn + pe[(size_t)lq * CC + c] + lp[(size_t)lq * CC + c]);
    } else if (bid < BLQ + BTP) {
        // ---- level-0 rows: copy x + LN2 ----
        int btp = bid - BLQ;
        size_t rowoff = (size_t)btp * NLVL * CC;
        float v = x[rowoff + c];
        g_XCAT[rowoff + c] = v;

        __shared__ float sh2[8];
        float s = v;
        for (int o = 16; o > 0; o >>= 1) s += __shfl_xor_sync(0xffffffffu, s, o);
        if ((c & 31) == 0) sh2[c >> 5] = s;
        __syncthreads();
        float mean = (sh2[0] + sh2[1] + sh2[2] + sh2[3]) * (1.f / CC);
        float dv = v - mean;
        float q2 = dv * dv;
        for (int o = 16; o > 0; o >>= 1) q2 += __shfl_xor_sync(0xffffffffu, q2, o);
        if ((c & 31) == 0) sh2[4 + (c >> 5)] = q2;
        __syncthreads();
        float var = (sh2[4] + sh2[5] + sh2[6] + sh2[7]) * (1.f / CC);
        g_XN2h[rowoff + c] = __float2half_rn(dv * rsqrtf(var + 1e-5f) * g2[c] + be2[c]);
    } else {
        // ---- weight conversion + bias pack ----
        int wb = bid - BLQ - BTP;             // 0..271
        if (wb == 0 && c < 128) {
            g_Bcat[c]       = b_off[c];
            g_Bcat[c + 128] = b_off[c + 128];
            g_Bcat[c + 256] = b_attn[c];
        }
        for (int idx = wb * 128 + c; idx < WTOTAL; idx += 272 * 128) {
            const float* src; int off;
            if      (idx < WOFF_ATTN) { src = w0; off = idx; }
            else if (idx < WOFF_VAL ) { src = w1; off = idx - WOFF_ATTN; }
            else if (idx < WOFF_OUT ) { src = w2; off = idx - WOFF_VAL; }
            else if (idx < WOFF_IN  ) { src = w3; off = idx - WOFF_OUT; }
            else if (idx < WOFF_OUTW) { src = w4; off = idx - WOFF_IN; }
            else if (idx < WOFF_FC1 ) { src = w5; off = idx - WOFF_OUTW; }
            else if (idx < WOFF_FC2 ) { src = w6; off = idx - WOFF_FC1; }
            else                      { src = w7; off = idx - WOFF_FC2; }
            g_Wh[idx] = __float2half_rn(src[off]);
        }
    }
}

// ---------------- deformable sampling: 16 threads/row, 16B gathers ---------
#define DEF_RPB 8
__device__ __forceinline__ void ld8h(float* dst, const __half* p, bool valid) {
    if (valid) {
        uint4 q = *(const uint4*)p;
        const __half2* hp = (const __half2*)&q;
#pragma unroll
        for (int j = 0; j < 4; j++) {
            float2 f = __half22float2(hp[j]);
            dst[2 * j] = f.x; dst[2 * j + 1] = f.y;
        }
    } else {
#pragma unroll
        for (int j = 0; j < 8; j++) dst[j] = 0.f;
    }
}

__global__ __launch_bounds__(128) void k_deform(const float* __restrict__ refp)
{
    __shared__ float sOFF[DEF_RPB][384];
    const int row0 = blockIdx.x * DEF_RPB;
    const int tid = threadIdx.x;

    for (int idx = tid; idx < DEF_RPB * 192; idx += 128) {
        int rr = idx / 192, c2 = idx - rr * 192;
        float2 v = __half22float2(*(const __half2*)(g_OFFAWh + (size_t)(row0 + rr) * 384 + c2 * 2));
        sOFF[rr][c2 * 2 + 0] = v.x;
        sOFF[rr][c2 * 2 + 1] = v.y;
    }
    __syncthreads();

    const int rr = tid >> 4;
    const int s = tid & 15;
    const int row = row0 + rr;
    const int b = row / LQ; const int lq = row - b * LQ;
    const int tp = lq >> 2; const int p = tp % PP; const int t = tp / PP;
    const int h = s >> 1, dq = s & 1;
    const float refx = refp[(((size_t)b * TT + t) * PP + p) * 2 + 0];
    const float refy = refp[(((size_t)b * TT + t) * PP + p) * 2 + 1];

    const float* awp = &sOFF[rr][256 + h * 16];
    float w[16], mx = -1e30f;
#pragma unroll
    for (int i = 0; i < 16; i++) { w[i] = awp[i]; mx = fmaxf(mx, w[i]); }
    float den = 0.f;
#pragma unroll
    for (int i = 0; i < 16; i++) { w[i] = expf(w[i] - mx); den += w[i]; }
    float inv = 1.f / den;

    const float*  offp  = &sOFF[rr][h * 32];
    const __half* vbase = g_VALh + (size_t)b * LQ * CC + h * 16 + dq * 8;
    float acc[8];
#pragma unroll
    for (int j = 0; j < 8; j++) acc[j] = 0.f;

#pragma unroll
    for (int l = 0; l < LL; l++) {
#pragma unroll
        for (int pt = 0; pt < NPT; pt++) {
            float ox = offp[(l * 4 + pt) * 2 + 0];
            float oy = offp[(l * 4 + pt) * 2 + 1];
            float fx = refx * PP + ox - 0.5f;
            float fy = refy * TT + oy - 0.5f;
            float x0f = floorf(fx), y0f = floorf(fy);
            int x0 = (int)x0f, y0 = (int)y0f;
            float wx1 = fx - x0f, wy1 = fy - y0f;
            float wx0 = 1.f - wx1, wy0 = 1.f - wy1;
            bool xi0 = (x0 >= 0) && (x0 < PP);
            bool xi1 = (x0 + 1 >= 0) && (x0 + 1 < PP);
            bool yi0 = (y0 >= 0) && (y0 < TT);
            bool yi1 = (y0 + 1 >= 0) && (y0 + 1 < TT);
            float v00[8], v01[8], v10[8], v11[8];
            ld8h(v00, vbase + ((size_t)(y0 * PP + x0) * LL + l) * CC,           yi0 && xi0);
            ld8h(v01, vbase + ((size_t)(y0 * PP + x0 + 1) * LL + l) * CC,       yi0 && xi1);
            ld8h(v10, vbase + ((size_t)((y0 + 1) * PP + x0) * LL + l) * CC,     yi1 && xi0);
            ld8h(v11, vbase + ((size_t)((y0 + 1) * PP + x0 + 1) * LL + l) * CC, yi1 && xi1);
            float w00 = wy0 * wx0, w01 = wy0 * wx1, w10 = wy1 * wx0, w11 = wy1 * wx1;
            float ww = w[l * 4 + pt];
#pragma unroll
            for (int j = 0; j < 8; j++) {
                float sv = v00[j] * w00 + v01[j] * w01 + v10[j] * w10 + v11[j] * w11;
                acc[j] = fmaf(sv, ww, acc[j]);
            }
        }
    }
    __half2 ho[4];
#pragma unroll
    for (int j = 0; j < 4; j++)
        ho[j] = __floats2half2_rn(acc[2 * j] * inv, acc[2 * j + 1] * inv);
    *(uint4*)(g_Oh + (size_t)row * CC + h * 16 + dq * 8) = *(uint4*)ho;
}

// ---------------- per-(bt,head) self-attention (fp16 QKV) ------------------
__global__ void k_attn()
{
    int bt = blockIdx.x, h = blockIdx.y;
    __shared__ float Qs[SS][DHH], Ks[SS][DHH], Vs[SS][DHH];
    int tid = threadIdx.x;
    for (int i = tid; i < SS * DHH; i += 128) {
        int s = i >> 4, d = i & 15;
        const __half* base = g_QKVh + ((size_t)bt * SS + s) * 384 + h * 16 + d;
        Qs[s][d] = __half2float(base[0]);
        Ks[s][d] = __half2float(base[128]);
        Vs[s][d] = __half2float(base[256]);
    }
    __syncthreads();
    if (tid < SS) {
        float qv[16];
#pragma unroll
        for (int d = 0; d < 16; d++) qv[d] = Qs[tid][d];
        float mx = -1e30f;
        for (int k = 0; k < SS; k++) {
            float sdot = 0.f;
#pragma unroll
            for (int d = 0; d < 16; d++) sdot = fmaf(qv[d], Ks[k][d], sdot);
            mx = fmaxf(mx, sdot * 0.25f);
        }
        float den = 0.f, o[16];
#pragma unroll
        for (int d = 0; d < 16; d++) o[d] = 0.f;
        for (int k = 0; k < SS; k++) {
            float sdot = 0.f;
#pragma unroll
            for (int d = 0; d < 16; d++) sdot = fmaf(qv[d], Ks[k][d], sdot);
            float e = expf(sdot * 0.25f - mx);
            den += e;
#pragma unroll
            for (int d = 0; d < 16; d++) o[d] = fmaf(e, Vs[k][d], o[d]);
        }
        float inv = 1.f / den;
        __half* outp = g_ATTOh + ((size_t)bt * SS + tid) * CC + h * 16;
#pragma unroll
        for (int d = 0; d < 16; d++) outp[d] = __float2half_rn(o[d] * inv);
    }
}

// ---------------- host launch ----------------------------------------------
static inline void launch_small(const __half* A, const __half* W, const float* bias,
                                const float* res, void* out, int M, int N, int K,
                                int epi, int outHalf, int perm = 0,
                                const float* lnG = nullptr, const float* lnB = nullptr,
                                __half* out2 = nullptr)
{
    dim3 grid(N / 128, (M + 63) / 64);
    k_gemm_h<<<grid, 128, GEMM_SMEM>>>(A, W, bias, res ? res : (const float*)A,
                                       out, M, N, K, epi, outHalf, perm, lnG, lnB, out2);
}
static inline void launch_big(const __half* A, const __half* W, const float* bias,
                              const float* res, void* out, int M, int N, int K,
                              int epi, int outHalf)
{
    dim3 grid(N / 128, (M + 127) / 128);
    k_gemm_big<<<grid, 256, BIG_SMEM>>>(A, W, bias, res ? res : (const float*)A,
                                        out, M, N, K, epi, outHalf);
}

extern "C" void kernel_launch(void* const* d_in, const int* in_sizes, int n_in,
                              void* d_out, int out_size)
{
    (void)in_sizes; (void)n_in; (void)out_size;
    const float* x        = (const float*)d_in[0];
    const float* refp     = (const float*)d_in[1];
    const float* pe_buf   = (const float*)d_in[2];
    const float* learn_pos= (const float*)d_in[3];
    const float* w_off    = (const float*)d_in[4];
    const float* b_off    = (const float*)d_in[5];
    const float* w_attn   = (const float*)d_in[6];
    const float* b_attn   = (const float*)d_in[7];
    const float* w_val    = (const float*)d_in[8];
    const float* b_val    = (const float*)d_in[9];
    const float* w_out    = (const float*)d_in[10];
    const float* b_out    = (const float*)d_in[11];
    const float* in_w     = (const float*)d_in[12];
    const float* in_b     = (const float*)d_in[13];
    const float* out_w    = (const float*)d_in[14];
    const float* b_out2   = (const float*)d_in[15];
    const float* fc1_w    = (const float*)d_in[16];
    const float* fc1_b    = (const float*)d_in[17];
    const float* fc2_w    = (const float*)d_in[18];
    const float* fc2_b    = (const float*)d_in[19];
    const float* g1       = (const float*)d_in[20];
    const float* be1      = (const float*)d_in[21];
    const float* g2       = (const float*)d_in[22];
    const float* be2      = (const float*)d_in[23];
    const float* g3       = (const float*)d_in[24];
    const float* be3      = (const float*)d_in[25];
    float* out = (float*)d_out;

    cudaFuncSetAttribute(k_gemm_h,   cudaFuncAttributeMaxDynamicSharedMemorySize, GEMM_SMEM);
    cudaFuncSetAttribute(k_projs,    cudaFuncAttributeMaxDynamicSharedMemorySize, GEMM_SMEM);
    cudaFuncSetAttribute(k_gemm_big, cudaFuncAttributeMaxDynamicSharedMemorySize, BIG_SMEM);

    float *pXCAT, *pXCAT2;
    __half *pOh, *pXN2h, *pQKVh, *pATTOh, *pXN3h, *pHIDh, *pWh;
    cudaGetSymbolAddress((void**)&pXCAT,  g_XCAT);
    cudaGetSymbolAddress((void**)&pXCAT2, g_XCAT2);
    cudaGetSymbolAddress((void**)&pOh,    g_Oh);
    cudaGetSymbolAddress((void**)&pXN2h,  g_XN2h);
    cudaGetSymbolAddress((void**)&pQKVh,  g_QKVh);
    cudaGetSymbolAddress((void**)&pATTOh, g_ATTOh);
    cudaGetSymbolAddress((void**)&pXN3h,  g_XN3h);
    cudaGetSymbolAddress((void**)&pHIDh,  g_HIDh);
    cudaGetSymbolAddress((void**)&pWh,    g_Wh);

    // 1) merged prologue: LN1 + lvl0(LN2) + weight cvt
    k_pre<<<BLQ + BTP + 272, 128>>>(x, pe_buf, learn_pos, g1, be1, g2, be2,
                                    w_off, w_attn, w_val, w_out, in_w, out_w,
                                    fc1_w, fc2_w, b_off, b_attn);
    // 2) merged projections: offaw (N=384) + val (N=128) -> fp16
    {
        dim3 grid(4, (BLQ + 63) / 64);
        k_projs<<<grid, 128, GEMM_SMEM>>>(b_val);
    }
    // 3) deformable sampling
    k_deform<<<BLQ / DEF_RPB, 128>>>(refp);
    // 4) out-proj + residual(from x, permuted) + concat + fused LN2 [epi3, perm]
    launch_small(pOh, pWh + WOFF_OUT, b_out, x, pXCAT, BLQ, 128, CC, 3, 0, 1,
                 g2, be2, pXN2h);
    // 5) QKV GEMM (N=384) -> fp16  [BIG]
    launch_big(pXN2h, pWh + WOFF_IN, in_b, nullptr, pQKVh, TOK, 384, CC, 0, 1);
    // 6) self-attention
    k_attn<<<dim3(BB * TT, HH), 128>>>();
    // 7) attention out-proj + residual + fused LN3 [epi3]
    launch_small(pATTOh, pWh + WOFF_OUTW, b_out2, pXCAT, pXCAT2, TOK, 128, CC, 3, 0, 0,
                 g3, be3, pXN3h);
    // 8) FC1 + GELU (N=512) -> fp16 [BIG]
    launch_big(pXN3h, pWh + WOFF_FC1, fc1_b, nullptr, pHIDh, TOK, 512, CC, 2, 1);
    // 9) FC2 + residual -> final output (K=512) [BIG]
    launch_big(pHIDh, pWh + WOFF_FC2, fc2_b, pXCAT2, out, TOK, 128, 512, 1, 0);
}